// round 14
// baseline (speedup 1.0000x reference)
#include <cuda_runtime.h>
#include <cstdint>
#include <math.h>

#define TOKENS 32768
#define NEXP   64
#define KDIM   2048
#define KC     32              // floats per K-chunk (2 k16 steps)
#define NCH    (KDIM / KC)     // 64 chunks
#define TILE_M 128
#define TPB    256
#define TMARG  0.01f           // flip-safety margin (~20 sigma of fp16 logit err)

#define A_BYTES     16384      // 128 rows x 128 B (32 fp32)
#define B_BYTES     4096       // 2 kb x 8 nf x 32 lanes x 8 B
#define STAGE_BYTES (A_BYTES + B_BYTES)   // 20480
#define NSTAGE      4
#define SMEM_BYTES  (NSTAGE * STAGE_BYTES) // 81920 -> 2 CTAs/SM

// W fragment-ready fp16: [kb16(128)][nf(8)][lane(32)] = {b0, b1}
__device__ uint2 g_wb[128 * 8 * 32];        // 256 KB
__device__ unsigned char g_flag[TOKENS];    // 1 = needs exact re-rank

static __device__ __forceinline__ uint32_t fpack(float hi, float lo) {
    uint32_t d;
    asm("cvt.rn.f16x2.f32 %0, %1, %2;" : "=r"(d) : "f"(hi), "f"(lo));
    return d;
}
static __device__ __forceinline__ void mma16(float* d, const uint32_t* a,
                                             uint32_t b0, uint32_t b1) {
    asm volatile(
        "mma.sync.aligned.m16n8k16.row.col.f32.f16.f16.f32 "
        "{%0,%1,%2,%3}, {%4,%5,%6,%7}, {%8,%9}, {%0,%1,%2,%3};"
        : "+f"(d[0]), "+f"(d[1]), "+f"(d[2]), "+f"(d[3])
        : "r"(a[0]), "r"(a[1]), "r"(a[2]), "r"(a[3]), "r"(b0), "r"(b1));
}
static __device__ __forceinline__ uint32_t s2u(const void* p) {
    uint32_t a;
    asm("{ .reg .u64 t; cvta.to.shared.u64 t, %1; cvt.u32.u64 %0, t; }" : "=r"(a) : "l"(p));
    return a;
}
static __device__ __forceinline__ void cp16(uint32_t dst, const void* src) {
    asm volatile("cp.async.ca.shared.global [%0], [%1], 16;"
                 :: "r"(dst), "l"(src) : "memory");
}

// top-2 (indexed) + top-3 value merge across lanes
static __device__ __forceinline__ void merge23(float& v1, int& i1, float& v2, int& i2,
                                               float& v3, int off) {
    float w1 = __shfl_xor_sync(0xffffffffu, v1, off);
    int   j1 = __shfl_xor_sync(0xffffffffu, i1, off);
    float w2 = __shfl_xor_sync(0xffffffffu, v2, off);
    int   j2 = __shfl_xor_sync(0xffffffffu, i2, off);
    float w3 = __shfl_xor_sync(0xffffffffu, v3, off);
    float z3 = fmaxf(fmaxf(fminf(v1, w2), fminf(v2, w1)), fmaxf(v3, w3));
    bool mine = (v1 > w1) || (v1 == w1 && i1 < j1);
    float l1v = mine ? w1 : v1;  int l1i = mine ? j1 : i1;
    float s2v = mine ? v2 : w2;  int s2i = mine ? i2 : j2;
    float nv1 = mine ? v1 : w1;  int ni1 = mine ? i1 : j1;
    bool sec = (s2v > l1v) || (s2v == l1v && s2i < l1i);
    v1 = nv1;  i1 = ni1;
    v2 = sec ? s2v : l1v;  i2 = sec ? s2i : l1i;
    v3 = z3;
}

// ---- prep: W -> fragment-ready fp16 (once per launch) ----
extern "C" __global__ void __launch_bounds__(256)
prep_w(const float* __restrict__ W)
{
    int idx  = blockIdx.x * 256 + threadIdx.x;  // 0..32767
    int lane = idx & 31;
    int nf   = (idx >> 5) & 7;
    int kb   = idx >> 8;                        // k16 block 0..127
    int g = lane >> 2, t = lane & 3;
    const float* wr = W + (size_t)(nf * 8 + g) * KDIM + kb * 16;
    uint2 r;
    r.x = fpack(wr[2 * t + 1], wr[2 * t]);          // b0: k = 2t, 2t+1
    r.y = fpack(wr[2 * t + 9], wr[2 * t + 8]);      // b1: k = 2t+8, 2t+9
    g_wb[idx] = r;
}

extern "C" __global__ void __launch_bounds__(TPB, 2)
router_f16(const float* __restrict__ X, float* __restrict__ out)
{
    extern __shared__ char smem[];
    const uint32_t sbase = s2u(smem);
    const int tid  = threadIdx.x;
    const int wid  = tid >> 5;
    const int lane = tid & 31;
    const int g    = lane >> 2;
    const int t    = lane & 3;
    const int W0   = wid * 16;            // this warp's row base
    const int blockM = blockIdx.x * TILE_M;

    // issue stage (c & 3) <- chunk c : A raw fp32 (swizzled 16B granules) + B fp16
    #define ISSUE(c)                                                            \
        {                                                                       \
            uint32_t dstA = sbase + ((c) & 3) * STAGE_BYTES;                    \
            _Pragma("unroll")                                                   \
            for (int j = 0; j < 4; j++) {                                       \
                int si = tid + 256 * j;      /* 0..1023 */                      \
                int row = si >> 3, chk = si & 7;                                \
                cp16(dstA + row * 128 + ((chk ^ (2 * (row & 3))) * 16),         \
                     X + (size_t)(blockM + row) * KDIM + (size_t)(c) * KC       \
                       + chk * 4);                                              \
            }                                                                   \
            cp16(dstA + A_BYTES + tid * 16,                                     \
                 reinterpret_cast<const uint4*>(g_wb) + (c) * 256 + tid);       \
        }
    #define COMMIT() asm volatile("cp.async.commit_group;" ::: "memory")

    float acc[8][4];
    #pragma unroll
    for (int nf = 0; nf < 8; nf++)
        #pragma unroll
        for (int u = 0; u < 4; u++) acc[nf][u] = 0.0f;

    // prologue: 3 stages in flight
    ISSUE(0); COMMIT();
    ISSUE(1); COMMIT();
    ISSUE(2); COMMIT();

    for (int c = 0; c < NCH; c++) {
        asm volatile("cp.async.wait_group %0;" :: "n"(2) : "memory");
        __syncthreads();   // stage c visible to all; stage (c+3)&3 fully consumed

        const int s = c & 3;
        const char* aS = smem + s * STAGE_BYTES;
        const uint2* sB = reinterpret_cast<const uint2*>(aS + A_BYTES);

        #pragma unroll
        for (int kb = 0; kb < 2; kb++) {
            uint32_t ah[4];
            {
                const int h  = t >> 1;
                const int o  = 8 * (t & 1);
                const int sw = 2 * (g & 3);
                const char* rp = aS + (size_t)(W0 + g) * 128;
                float2 f0 = *reinterpret_cast<const float2*>(
                    rp + ((kb * 4 + h) ^ sw) * 16 + o);
                float2 f1 = *reinterpret_cast<const float2*>(
                    rp + 1024 + (((kb * 4 + h) ^ sw) * 16) + o);
                float2 f2 = *reinterpret_cast<const float2*>(
                    rp + ((kb * 4 + 2 + h) ^ sw) * 16 + o);
                float2 f3 = *reinterpret_cast<const float2*>(
                    rp + 1024 + (((kb * 4 + 2 + h) ^ sw) * 16) + o);
                ah[0] = fpack(f0.y, f0.x);   // (row, k=2t,2t+1)
                ah[1] = fpack(f1.y, f1.x);   // (row+8, same k)
                ah[2] = fpack(f2.y, f2.x);   // (row, k+8)
                ah[3] = fpack(f3.y, f3.x);   // (row+8, k+8)
            }
            #pragma unroll
            for (int nf = 0; nf < 8; nf++) {
                uint2 b = sB[(kb * 8 + nf) * 32 + lane];
                mma16(acc[nf], ah, b.x, b.y);
            }
        }

        if (c + 3 < NCH) ISSUE(c + 3);
        COMMIT();   // empty groups at the tail keep the wait_group count aligned
    }

    // ------------- epilogue: logits + approx top-3 + flag -------------
    float* outIdx = out;
    float* outWgt = out + TOKENS * 2;
    float* outLog = out + TOKENS * 4;

    #pragma unroll
    for (int h = 0; h < 2; h++) {
        const int row = W0 + h * 8 + g;
        const int tok = blockM + row;

        float v1 = -INFINITY, v2 = -INFINITY, v3 = -INFINITY;
        int   i1 = 0, i2 = 0;
        #pragma unroll
        for (int nf = 0; nf < 8; nf++) {
            #pragma unroll
            for (int u = 0; u < 2; u++) {
                float v  = acc[nf][2 * h + u];
                int   id = nf * 8 + 2 * t + u;
                if (v > v1)      { v3 = v2; v2 = v1; i2 = i1; v1 = v; i1 = id; }
                else if (v > v2) { v3 = v2; v2 = v;  i2 = id; }
                else if (v > v3) { v3 = v; }
            }
        }
        merge23(v1, i1, v2, i2, v3, 1);
        merge23(v1, i1, v2, i2, v3, 2);

        float* lr = outLog + (size_t)tok * NEXP;
        #pragma unroll
        for (int nf = 0; nf < 8; nf++) {
            float2 o = make_float2(acc[nf][2 * h], acc[nf][2 * h + 1]);
            *reinterpret_cast<float2*>(lr + nf * 8 + 2 * t) = o;
        }

        if (t == 0) {
            float e2  = expf(v2 - v1);          // v1 >= v2 -> stable
            float inv = 1.0f / (1.0f + e2);
            outIdx[tok * 2]     = (float)i1;
            outIdx[tok * 2 + 1] = (float)i2;
            outWgt[tok * 2]     = inv;
            outWgt[tok * 2 + 1] = e2 * inv;
            g_flag[tok] = ((v1 - v2 < TMARG) || (v2 - v3 < TMARG)) ? 1 : 0;
        }
    }
}

// ---- exact re-rank of flagged tokens (fp32 from gmem) ----
extern "C" __global__ void __launch_bounds__(256)
rerank(const float* __restrict__ X, const float* __restrict__ W,
       float* __restrict__ out)
{
    const int wid  = threadIdx.x >> 5;
    const int lane = threadIdx.x & 31;
    float* outIdx = out;
    float* outWgt = out + TOKENS * 2;
    const float* outLog = out + TOKENS * 4;

    for (int it = 0; it < 4; it++) {
        const int tok = blockIdx.x * 8 + wid + it * 8192;
        if (!g_flag[tok]) continue;

        const float* lr = outLog + (size_t)tok * NEXP;
        float2 lv = reinterpret_cast<const float2*>(lr)[lane];
        float a = fmaxf(lv.x, lv.y), b = fminf(lv.x, lv.y);
        #pragma unroll
        for (int off = 16; off > 0; off >>= 1) {
            float oa = __shfl_xor_sync(0xffffffffu, a, off);
            float ob = __shfl_xor_sync(0xffffffffu, b, off);
            float na = fmaxf(a, oa);
            b = fmaxf(fminf(a, oa), fmaxf(b, ob));
            a = na;
        }
        const float thresh = b - TMARG;

        float xr[64];
        const float* xrow = X + (size_t)tok * KDIM;
        #pragma unroll
        for (int j = 0; j < 64; j++) xr[j] = xrow[lane + 32 * j];

        float e1 = -INFINITY, e2v = -INFINITY;
        int   j1 = 0, j2 = 0;
        for (int e = 0; e < NEXP; e++) {
            float lg = __shfl_sync(0xffffffffu, (lane == (e >> 1))
                                   ? ((e & 1) ? lv.y : lv.x) : 0.0f, e >> 1);
            if (lg >= thresh) {
                const float* wr = W + (size_t)e * KDIM;
                float s = 0.0f;
                #pragma unroll
                for (int j = 0; j < 64; j++) s = fmaf(xr[j], wr[lane + 32 * j], s);
                #pragma unroll
                for (int off = 16; off > 0; off >>= 1)
                    s += __shfl_xor_sync(0xffffffffu, s, off);
                if (s > e1)       { e2v = e1; j2 = j1; e1 = s; j1 = e; }
                else if (s > e2v) { e2v = s;  j2 = e; }
            }
        }
        if (lane == 0) {
            float ex  = expf(e2v - e1);
            float inv = 1.0f / (1.0f + ex);
            outIdx[tok * 2]     = (float)j1;
            outIdx[tok * 2 + 1] = (float)j2;
            outWgt[tok * 2]     = inv;
            outWgt[tok * 2 + 1] = ex * inv;
        }
    }
}

extern "C" void kernel_launch(void* const* d_in, const int* in_sizes, int n_in,
                              void* d_out, int out_size)
{
    const float* X = (const float*)d_in[0];   // [32768, 2048] fp32
    const float* W = (const float*)d_in[1];   // [64, 2048] fp32
    float* out = (float*)d_out;

    prep_w<<<128, 256>>>(W);

    cudaFuncSetAttribute(router_f16,
                         cudaFuncAttributeMaxDynamicSharedMemorySize, SMEM_BYTES);
    router_f16<<<TOKENS / TILE_M, TPB, SMEM_BYTES>>>(X, out);

    rerank<<<1024, 256>>>(X, (const float*)d_in[1], out);
}

// round 16
// speedup vs baseline: 1.3506x; 1.3506x over previous
#include <cuda_runtime.h>
#include <cstdint>
#include <math.h>

#define TOKENS 32768
#define NEXP   64
#define KDIM   2048
#define KC     64              // floats per K-chunk (4 k16 steps)
#define NCH    (KDIM / KC)     // 32 chunks
#define TILE_M 128
#define TPB    256
#define TMARG  0.01f           // flip-safety margin (~20 sigma of fp16 logit err)

__device__ unsigned char g_flag[TOKENS];    // 1 = needs exact re-rank

static __device__ __forceinline__ uint32_t fpack(float hi, float lo) {
    uint32_t d;
    asm("cvt.rn.f16x2.f32 %0, %1, %2;" : "=r"(d) : "f"(hi), "f"(lo));
    return d;
}
static __device__ __forceinline__ void mma16(float* d, const uint32_t* a,
                                             uint32_t b0, uint32_t b1) {
    asm volatile(
        "mma.sync.aligned.m16n8k16.row.col.f32.f16.f16.f32 "
        "{%0,%1,%2,%3}, {%4,%5,%6,%7}, {%8,%9}, {%0,%1,%2,%3};"
        : "+f"(d[0]), "+f"(d[1]), "+f"(d[2]), "+f"(d[3])
        : "r"(a[0]), "r"(a[1]), "r"(a[2]), "r"(a[3]), "r"(b0), "r"(b1));
}

// top-2 (indexed) + top-3 value merge across lanes
static __device__ __forceinline__ void merge23(float& v1, int& i1, float& v2, int& i2,
                                               float& v3, int off) {
    float w1 = __shfl_xor_sync(0xffffffffu, v1, off);
    int   j1 = __shfl_xor_sync(0xffffffffu, i1, off);
    float w2 = __shfl_xor_sync(0xffffffffu, v2, off);
    int   j2 = __shfl_xor_sync(0xffffffffu, i2, off);
    float w3 = __shfl_xor_sync(0xffffffffu, v3, off);
    float z3 = fmaxf(fmaxf(fminf(v1, w2), fminf(v2, w1)), fmaxf(v3, w3));
    bool mine = (v1 > w1) || (v1 == w1 && i1 < j1);
    float l1v = mine ? w1 : v1;  int l1i = mine ? j1 : i1;
    float s2v = mine ? v2 : w2;  int s2i = mine ? i2 : j2;
    float nv1 = mine ? v1 : w1;  int ni1 = mine ? i1 : j1;
    bool sec = (s2v > l1v) || (s2v == l1v && s2i < l1i);
    v1 = nv1;  i1 = ni1;
    v2 = sec ? s2v : l1v;  i2 = sec ? s2i : l1i;
    v3 = z3;
}

// SMEM per stage (uint4): aH[1024] (16KB fp16 A) | B[512] (8KB fp16 frags) = 1536 u4
#define STAGE_U4  1536
#define SMEM_BYTES (2 * STAGE_U4 * 16)   // 49152 -> 2 CTAs/SM

extern "C" __global__ void __launch_bounds__(TPB, 2)
router_f16(const float* __restrict__ X, const float* __restrict__ Wm,
           float* __restrict__ out)
{
    extern __shared__ uint4 sm4[];
    const int tid  = threadIdx.x;
    const int wid  = tid >> 5;
    const int lane = tid & 31;
    const int g    = lane >> 2;
    const int t    = lane & 3;
    const int blockM = blockIdx.x * TILE_M;

    if (wid >= 4) {
        // ------------- producers: warps 4..7 -------------
        const int p = tid - 128;   // 0..127
        float4 xa[8], xb[8];       // A chunk: 64 floats/thread
        float2 bw0[8], bw1[8];     // W fragments: 8 uint2-to-be per thread

        // A chunk c -> regs (16 LDG.128/thread)
        #define PLOAD(c)                                                        \
            {                                                                   \
                _Pragma("unroll")                                               \
                for (int j = 0; j < 8; j++) {                                   \
                    int s_idx = p + 128 * j;          /* 0..1023 */             \
                    int row = s_idx >> 3, q = s_idx & 7;                        \
                    const float* src = X + (size_t)(blockM + row) * KDIM        \
                                         + (size_t)(c) * KC + q * 8;            \
                    xa[j] = reinterpret_cast<const float4*>(src)[0];            \
                    xb[j] = reinterpret_cast<const float4*>(src)[1];            \
                }                                                               \
            }
        // W fragments for chunk c -> regs (16 LDG.64/thread, L2-hot)
        #define BLOAD(c)                                                        \
            {                                                                   \
                _Pragma("unroll")                                               \
                for (int j = 0; j < 8; j++) {                                   \
                    int si = p + 128 * j;             /* 0..1023 */             \
                    int kb = si >> 8;                 /* 0..3 local */          \
                    int nf = (si >> 5) & 7;                                     \
                    int ln = si & 31;                                           \
                    int gg = ln >> 2, tt = ln & 3;                              \
                    const float* wr = Wm + (size_t)(nf * 8 + gg) * KDIM         \
                                         + ((size_t)(c) * 4 + kb) * 16;         \
                    bw0[j] = *reinterpret_cast<const float2*>(wr + 2 * tt);     \
                    bw1[j] = *reinterpret_cast<const float2*>(wr + 2 * tt + 8); \
                }                                                               \
            }
        // convert + store chunk c into stage (c&1)
        #define PSTORE(c)                                                       \
            {                                                                   \
                uint4* aH = sm4 + ((c) & 1) * STAGE_U4;                         \
                uint2* sBs = reinterpret_cast<uint2*>(aH + 1024);               \
                _Pragma("unroll")                                               \
                for (int j = 0; j < 8; j++) {                                   \
                    int s_idx = p + 128 * j;                                    \
                    int row = s_idx >> 3, q = s_idx & 7;                        \
                    uint4 H;                                                    \
                    H.x = fpack(xa[j].y, xa[j].x);                              \
                    H.y = fpack(xa[j].w, xa[j].z);                              \
                    H.z = fpack(xb[j].y, xb[j].x);                              \
                    H.w = fpack(xb[j].w, xb[j].z);                              \
                    aH[q * 128 + (row ^ q)] = H;                                \
                    uint2 r;                                                    \
                    r.x = fpack(bw0[j].y, bw0[j].x);                            \
                    r.y = fpack(bw1[j].y, bw1[j].x);                            \
                    sBs[s_idx] = r;                                             \
                }                                                               \
            }

        PLOAD(0); BLOAD(0);
        PSTORE(0);
        PLOAD(1); BLOAD(1);
        __syncthreads();

        for (int c = 0; c < NCH; c++) {
            if (c + 1 < NCH) {
                PSTORE(c + 1);
                if (c + 2 < NCH) { PLOAD(c + 2); BLOAD(c + 2); }
            }
            __syncthreads();
        }
        return;
    }

    // ------------- consumers: warps 0..3, tile m32 x n64 (identical to R10) ----
    float acc[2][8][4];
    #pragma unroll
    for (int mf = 0; mf < 2; mf++)
        #pragma unroll
        for (int nf = 0; nf < 8; nf++)
            #pragma unroll
            for (int u = 0; u < 4; u++) acc[mf][nf][u] = 0.0f;

    const int wbase = wid * 32;
    __syncthreads();   // match producer prologue

    for (int c = 0; c < NCH; c++) {
        const int s = c & 1;
        const uint32_t* aH = reinterpret_cast<const uint32_t*>(sm4 + s * STAGE_U4);
        const uint2*    sB = reinterpret_cast<const uint2*>(sm4 + s * STAGE_U4 + 1024);

        #pragma unroll
        for (int kb = 0; kb < 4; kb++) {
            const int q0 = 2 * kb, q1 = 2 * kb + 1;
            uint32_t ah[2][4];
            #pragma unroll
            for (int mf = 0; mf < 2; mf++) {
                const int R0 = wbase + mf * 16 + g;
                const int i0 = (q0 * 128 + (R0 ^ q0)) * 4 + t;
                const int i2 = (q1 * 128 + (R0 ^ q1)) * 4 + t;
                ah[mf][0] = aH[i0];       ah[mf][1] = aH[i0 + 32];
                ah[mf][2] = aH[i2];       ah[mf][3] = aH[i2 + 32];
            }
            uint2 b[8];
            #pragma unroll
            for (int nf = 0; nf < 8; nf++)
                b[nf] = sB[(kb * 8 + nf) * 32 + lane];
            #pragma unroll
            for (int nf = 0; nf < 8; nf++)
                #pragma unroll
                for (int mf = 0; mf < 2; mf++)
                    mma16(acc[mf][nf], ah[mf], b[nf].x, b[nf].y);
        }
        __syncthreads();
    }

    // ------------- epilogue: logits + approx top-3 + flag -------------
    float* outIdx = out;
    float* outWgt = out + TOKENS * 2;
    float* outLog = out + TOKENS * 4;

    #pragma unroll
    for (int mf = 0; mf < 2; mf++) {
        #pragma unroll
        for (int h = 0; h < 2; h++) {
            const int row = wbase + mf * 16 + h * 8 + g;
            const int tok = blockM + row;

            float v1 = -INFINITY, v2 = -INFINITY, v3 = -INFINITY;
            int   i1 = 0, i2 = 0;
            #pragma unroll
            for (int nf = 0; nf < 8; nf++) {
                #pragma unroll
                for (int u = 0; u < 2; u++) {
                    float v  = acc[mf][nf][2 * h + u];
                    int   id = nf * 8 + 2 * t + u;
                    if (v > v1)      { v3 = v2; v2 = v1; i2 = i1; v1 = v; i1 = id; }
                    else if (v > v2) { v3 = v2; v2 = v;  i2 = id; }
                    else if (v > v3) { v3 = v; }
                }
            }
            merge23(v1, i1, v2, i2, v3, 1);
            merge23(v1, i1, v2, i2, v3, 2);

            float* lr = outLog + (size_t)tok * NEXP;
            #pragma unroll
            for (int nf = 0; nf < 8; nf++) {
                float2 o = make_float2(acc[mf][nf][2 * h], acc[mf][nf][2 * h + 1]);
                *reinterpret_cast<float2*>(lr + nf * 8 + 2 * t) = o;
            }

            if (t == 0) {
                float e2  = expf(v2 - v1);          // v1 >= v2 -> stable
                float inv = 1.0f / (1.0f + e2);
                outIdx[tok * 2]     = (float)i1;
                outIdx[tok * 2 + 1] = (float)i2;
                outWgt[tok * 2]     = inv;
                outWgt[tok * 2 + 1] = e2 * inv;
                g_flag[tok] = ((v1 - v2 < TMARG) || (v2 - v3 < TMARG)) ? 1 : 0;
            }
        }
    }
}

// ---- exact re-rank of flagged tokens (fp32 from gmem) ----
extern "C" __global__ void __launch_bounds__(256)
rerank(const float* __restrict__ X, const float* __restrict__ W,
       float* __restrict__ out)
{
    const int wid  = threadIdx.x >> 5;
    const int lane = threadIdx.x & 31;
    float* outIdx = out;
    float* outWgt = out + TOKENS * 2;
    const float* outLog = out + TOKENS * 4;

    for (int it = 0; it < 4; it++) {
        const int tok = blockIdx.x * 8 + wid + it * 8192;
        if (!g_flag[tok]) continue;

        const float* lr = outLog + (size_t)tok * NEXP;
        float2 lv = reinterpret_cast<const float2*>(lr)[lane];
        float a = fmaxf(lv.x, lv.y), b = fminf(lv.x, lv.y);
        #pragma unroll
        for (int off = 16; off > 0; off >>= 1) {
            float oa = __shfl_xor_sync(0xffffffffu, a, off);
            float ob = __shfl_xor_sync(0xffffffffu, b, off);
            float na = fmaxf(a, oa);
            b = fmaxf(fminf(a, oa), fmaxf(b, ob));
            a = na;
        }
        const float thresh = b - TMARG;

        float xr[64];
        const float* xrow = X + (size_t)tok * KDIM;
        #pragma unroll
        for (int j = 0; j < 64; j++) xr[j] = xrow[lane + 32 * j];

        float e1 = -INFINITY, e2v = -INFINITY;
        int   j1 = 0, j2 = 0;
        for (int e = 0; e < NEXP; e++) {
            float lg = __shfl_sync(0xffffffffu, (lane == (e >> 1))
                                   ? ((e & 1) ? lv.y : lv.x) : 0.0f, e >> 1);
            if (lg >= thresh) {
                const float* wr = W + (size_t)e * KDIM;
                float s = 0.0f;
                #pragma unroll
                for (int j = 0; j < 64; j++) s = fmaf(xr[j], wr[lane + 32 * j], s);
                #pragma unroll
                for (int off = 16; off > 0; off >>= 1)
                    s += __shfl_xor_sync(0xffffffffu, s, off);
                if (s > e1)       { e2v = e1; j2 = j1; e1 = s; j1 = e; }
                else if (s > e2v) { e2v = s;  j2 = e; }
            }
        }
        if (lane == 0) {
            float ex  = expf(e2v - e1);
            float inv = 1.0f / (1.0f + ex);
            outIdx[tok * 2]     = (float)j1;
            outIdx[tok * 2 + 1] = (float)j2;
            outWgt[tok * 2]     = inv;
            outWgt[tok * 2 + 1] = ex * inv;
        }
    }
}

extern "C" void kernel_launch(void* const* d_in, const int* in_sizes, int n_in,
                              void* d_out, int out_size)
{
    const float* X = (const float*)d_in[0];   // [32768, 2048] fp32
    const float* W = (const float*)d_in[1];   // [64, 2048] fp32
    float* out = (float*)d_out;

    cudaFuncSetAttribute(router_f16,
                         cudaFuncAttributeMaxDynamicSharedMemorySize, SMEM_BYTES);
    router_f16<<<TOKENS / TILE_M, TPB, SMEM_BYTES>>>(X, W, out);

    rerank<<<1024, 256>>>(X, W, out);
}

// round 17
// speedup vs baseline: 2.0743x; 1.5358x over previous
#include <cuda_runtime.h>
#include <cstdint>
#include <math.h>

#define TOKENS 32768
#define NEXP   64
#define KDIM   2048
#define KC     64              // floats per K-chunk (4 k16 steps)
#define NCH    (KDIM / KC)     // 32 chunks
#define TILE_M 128
#define TPB    256
#define TMARG  0.005f          // flip-safety margin (>=8 sigma of fp16 logit err)

// W fragment-ready fp16: [kb16(128)][nf(8)][lane(32)] = {b0, b1}
__device__ uint2 g_wb[128 * 8 * 32];        // 256 KB
__device__ int   g_cnt;                     // worklist counter
__device__ int   g_list[TOKENS];            // flagged-token worklist

static __device__ __forceinline__ uint32_t fpack(float hi, float lo) {
    uint32_t d;
    asm("cvt.rn.f16x2.f32 %0, %1, %2;" : "=r"(d) : "f"(hi), "f"(lo));
    return d;
}
static __device__ __forceinline__ void mma16(float* d, const uint32_t* a,
                                             uint32_t b0, uint32_t b1) {
    asm volatile(
        "mma.sync.aligned.m16n8k16.row.col.f32.f16.f16.f32 "
        "{%0,%1,%2,%3}, {%4,%5,%6,%7}, {%8,%9}, {%0,%1,%2,%3};"
        : "+f"(d[0]), "+f"(d[1]), "+f"(d[2]), "+f"(d[3])
        : "r"(a[0]), "r"(a[1]), "r"(a[2]), "r"(a[3]), "r"(b0), "r"(b1));
}
static __device__ __forceinline__ uint32_t s2u(const void* p) {
    uint32_t a;
    asm("{ .reg .u64 t; cvta.to.shared.u64 t, %1; cvt.u32.u64 %0, t; }" : "=r"(a) : "l"(p));
    return a;
}
static __device__ __forceinline__ void cp16(uint32_t dst, const void* src) {
    asm volatile("cp.async.ca.shared.global [%0], [%1], 16;"
                 :: "r"(dst), "l"(src) : "memory");
}

// top-2 (indexed) + top-3 value merge across lanes
static __device__ __forceinline__ void merge23(float& v1, int& i1, float& v2, int& i2,
                                               float& v3, int off) {
    float w1 = __shfl_xor_sync(0xffffffffu, v1, off);
    int   j1 = __shfl_xor_sync(0xffffffffu, i1, off);
    float w2 = __shfl_xor_sync(0xffffffffu, v2, off);
    int   j2 = __shfl_xor_sync(0xffffffffu, i2, off);
    float w3 = __shfl_xor_sync(0xffffffffu, v3, off);
    float z3 = fmaxf(fmaxf(fminf(v1, w2), fminf(v2, w1)), fmaxf(v3, w3));
    bool mine = (v1 > w1) || (v1 == w1 && i1 < j1);
    float l1v = mine ? w1 : v1;  int l1i = mine ? j1 : i1;
    float s2v = mine ? v2 : w2;  int s2i = mine ? i2 : j2;
    float nv1 = mine ? v1 : w1;  int ni1 = mine ? i1 : j1;
    bool sec = (s2v > l1v) || (s2v == l1v && s2i < l1i);
    v1 = nv1;  i1 = ni1;
    v2 = sec ? s2v : l1v;  i2 = sec ? s2i : l1i;
    v3 = z3;
}

// ---- prep: W -> fragment-ready fp16 + zero worklist counter ----
extern "C" __global__ void __launch_bounds__(256)
prep_w(const float* __restrict__ W)
{
    int idx  = blockIdx.x * 256 + threadIdx.x;  // 0..32767
    if (idx == 0) g_cnt = 0;
    int lane = idx & 31;
    int nf   = (idx >> 5) & 7;
    int kb   = idx >> 8;                        // k16 block 0..127
    int g = lane >> 2, t = lane & 3;
    const float* wr = W + (size_t)(nf * 8 + g) * KDIM + kb * 16;
    uint2 r;
    r.x = fpack(wr[2 * t + 1], wr[2 * t]);          // b0: k = 2t, 2t+1
    r.y = fpack(wr[2 * t + 9], wr[2 * t + 8]);      // b1: k = 2t+8, 2t+9
    g_wb[idx] = r;
}

// SMEM per stage (uint4): aH[1024] (16KB) | B[512] (8KB) = 1536 u4 = 24KB
#define STAGE_U4  1536
#define SMEM_BYTES (2 * STAGE_U4 * 16)   // 49152

extern "C" __global__ void __launch_bounds__(TPB, 2)
router_f16(const float* __restrict__ X, float* __restrict__ out)
{
    extern __shared__ uint4 sm4[];
    const int tid  = threadIdx.x;
    const int wid  = tid >> 5;
    const int lane = tid & 31;
    const int g    = lane >> 2;
    const int t    = lane & 3;
    const int blockM = blockIdx.x * TILE_M;

    if (wid >= 4) {
        // ------------- producers: warps 4..7 (R10 verbatim) -------------
        const int p = tid - 128;   // 0..127
        float4 xa[8], xb[8];       // one A chunk: 64 floats/thread

        #define PLOAD(c)                                                        \
            {                                                                   \
                _Pragma("unroll")                                               \
                for (int j = 0; j < 8; j++) {                                   \
                    int s_idx = p + 128 * j;          /* 0..1023 */             \
                    int row = s_idx >> 3, q = s_idx & 7;                        \
                    const float* src = X + (size_t)(blockM + row) * KDIM        \
                                         + (size_t)(c) * KC + q * 8;            \
                    xa[j] = reinterpret_cast<const float4*>(src)[0];            \
                    xb[j] = reinterpret_cast<const float4*>(src)[1];            \
                }                                                               \
            }
        #define PSTORE(c)                                                       \
            {                                                                   \
                uint4* aH = sm4 + ((c) & 1) * STAGE_U4;                         \
                _Pragma("unroll")                                               \
                for (int j = 0; j < 8; j++) {                                   \
                    int s_idx = p + 128 * j;                                    \
                    int row = s_idx >> 3, q = s_idx & 7;                        \
                    uint4 H;                                                    \
                    H.x = fpack(xa[j].y, xa[j].x);                              \
                    H.y = fpack(xa[j].w, xa[j].z);                              \
                    H.z = fpack(xb[j].y, xb[j].x);                              \
                    H.w = fpack(xb[j].w, xb[j].z);                              \
                    aH[q * 128 + (row ^ q)] = H;                                \
                }                                                               \
            }
        #define PCOPYB(c)                                                       \
            {                                                                   \
                uint32_t sB = s2u(sm4 + ((c) & 1) * STAGE_U4 + 1024);           \
                const uint4* wb4 = reinterpret_cast<const uint4*>(g_wb);        \
                _Pragma("unroll")                                               \
                for (int j = 0; j < 4; j++) {                                   \
                    int s_idx = p + 128 * j;          /* 0..511 */              \
                    cp16(sB + s_idx * 16, wb4 + (c) * 512 + s_idx);             \
                }                                                               \
                asm volatile("cp.async.commit_group;" ::: "memory");            \
            }
        #define PWAIT() asm volatile("cp.async.wait_group 0;" ::: "memory")

        PLOAD(0);
        PCOPYB(0);
        PSTORE(0);
        PLOAD(1);
        PWAIT();
        __syncthreads();

        for (int c = 0; c < NCH; c++) {
            if (c + 1 < NCH) {
                PCOPYB(c + 1);
                PSTORE(c + 1);
                if (c + 2 < NCH) PLOAD(c + 2);
                PWAIT();
            }
            __syncthreads();
        }
        return;
    }

    // ------------- consumers: warps 0..3, tile m32 x n64 (R10 verbatim) ------
    float acc[2][8][4];
    #pragma unroll
    for (int mf = 0; mf < 2; mf++)
        #pragma unroll
        for (int nf = 0; nf < 8; nf++)
            #pragma unroll
            for (int u = 0; u < 4; u++) acc[mf][nf][u] = 0.0f;

    const int wbase = wid * 32;
    __syncthreads();   // match producer prologue

    for (int c = 0; c < NCH; c++) {
        const int s = c & 1;
        const uint32_t* aH = reinterpret_cast<const uint32_t*>(sm4 + s * STAGE_U4);
        const uint2*    sB = reinterpret_cast<const uint2*>(sm4 + s * STAGE_U4 + 1024);

        #pragma unroll
        for (int kb = 0; kb < 4; kb++) {
            const int q0 = 2 * kb, q1 = 2 * kb + 1;
            uint32_t ah[2][4];
            #pragma unroll
            for (int mf = 0; mf < 2; mf++) {
                const int R0 = wbase + mf * 16 + g;
                const int i0 = (q0 * 128 + (R0 ^ q0)) * 4 + t;
                const int i2 = (q1 * 128 + (R0 ^ q1)) * 4 + t;
                ah[mf][0] = aH[i0];       ah[mf][1] = aH[i0 + 32];
                ah[mf][2] = aH[i2];       ah[mf][3] = aH[i2 + 32];
            }
            uint2 b[8];
            #pragma unroll
            for (int nf = 0; nf < 8; nf++)
                b[nf] = sB[(kb * 8 + nf) * 32 + lane];
            #pragma unroll
            for (int nf = 0; nf < 8; nf++)
                #pragma unroll
                for (int mf = 0; mf < 2; mf++)
                    mma16(acc[mf][nf], ah[mf], b[nf].x, b[nf].y);
        }
        __syncthreads();
    }

    // ------------- epilogue: logits + approx top-3 + worklist flag -------------
    float* outIdx = out;
    float* outWgt = out + TOKENS * 2;
    float* outLog = out + TOKENS * 4;

    #pragma unroll
    for (int mf = 0; mf < 2; mf++) {
        #pragma unroll
        for (int h = 0; h < 2; h++) {
            const int row = wbase + mf * 16 + h * 8 + g;
            const int tok = blockM + row;

            float v1 = -INFINITY, v2 = -INFINITY, v3 = -INFINITY;
            int   i1 = 0, i2 = 0;
            #pragma unroll
            for (int nf = 0; nf < 8; nf++) {
                #pragma unroll
                for (int u = 0; u < 2; u++) {
                    float v  = acc[mf][nf][2 * h + u];
                    int   id = nf * 8 + 2 * t + u;
                    if (v > v1)      { v3 = v2; v2 = v1; i2 = i1; v1 = v; i1 = id; }
                    else if (v > v2) { v3 = v2; v2 = v;  i2 = id; }
                    else if (v > v3) { v3 = v; }
                }
            }
            merge23(v1, i1, v2, i2, v3, 1);
            merge23(v1, i1, v2, i2, v3, 2);

            float* lr = outLog + (size_t)tok * NEXP;
            #pragma unroll
            for (int nf = 0; nf < 8; nf++) {
                float2 o = make_float2(acc[nf == 0 ? mf : mf][nf][2 * h],
                                       acc[mf][nf][2 * h + 1]);
                o.x = acc[mf][nf][2 * h];
                *reinterpret_cast<float2*>(lr + nf * 8 + 2 * t) = o;
            }

            if (t == 0) {
                float e2  = expf(v2 - v1);          // v1 >= v2 -> stable
                float inv = 1.0f / (1.0f + e2);
                outIdx[tok * 2]     = (float)i1;
                outIdx[tok * 2 + 1] = (float)i2;
                outWgt[tok * 2]     = inv;
                outWgt[tok * 2 + 1] = e2 * inv;
                if ((v1 - v2 < TMARG) || (v2 - v3 < TMARG)) {
                    int slot = atomicAdd(&g_cnt, 1);
                    g_list[slot] = tok;
                }
            }
        }
    }
}

// ---- exact re-rank of worklist tokens (fp32 from gmem, ballot-gated) ----
extern "C" __global__ void __launch_bounds__(256)
rerank(const float* __restrict__ X, const float* __restrict__ W,
       float* __restrict__ out)
{
    const int wid  = threadIdx.x >> 5;
    const int lane = threadIdx.x & 31;
    const int gw   = blockIdx.x * 8 + wid;
    const int nw   = gridDim.x * 8;
    float* outIdx = out;
    float* outWgt = out + TOKENS * 2;
    const float* outLog = out + TOKENS * 4;

    const int n = *(volatile int*)&g_cnt;

    for (int i = gw; i < n; i += nw) {
        const int tok = g_list[i];

        // approx v2 of the row (values only)
        const float* lr = outLog + (size_t)tok * NEXP;
        float2 lv = reinterpret_cast<const float2*>(lr)[lane];
        float a = fmaxf(lv.x, lv.y), b = fminf(lv.x, lv.y);
        #pragma unroll
        for (int off = 16; off > 0; off >>= 1) {
            float oa = __shfl_xor_sync(0xffffffffu, a, off);
            float ob = __shfl_xor_sync(0xffffffffu, b, off);
            float na = fmaxf(a, oa);
            b = fmaxf(fminf(a, oa), fmaxf(b, ob));
            a = na;
        }
        const float thresh = b - TMARG;

        // candidate masks: lane l holds experts 2l (lv.x) and 2l+1 (lv.y)
        const unsigned mx = __ballot_sync(0xffffffffu, lv.x >= thresh);
        const unsigned my = __ballot_sync(0xffffffffu, lv.y >= thresh);

        // preload X row: k = lane + 32*j
        float xr[64];
        const float* xrow = X + (size_t)tok * KDIM;
        #pragma unroll
        for (int j = 0; j < 64; j++) xr[j] = xrow[lane + 32 * j];

        // exact dots for candidates, ascending e -> stable ties
        float e1 = -INFINITY, e2v = -INFINITY;
        int   j1 = 0, j2 = 0;
        for (int e = 0; e < NEXP; e++) {
            unsigned m = (e & 1) ? my : mx;
            if (!((m >> (e >> 1)) & 1u)) continue;
            const float* wr = W + (size_t)e * KDIM;
            float s = 0.0f;
            #pragma unroll
            for (int j = 0; j < 64; j++) s = fmaf(xr[j], wr[lane + 32 * j], s);
            #pragma unroll
            for (int off = 16; off > 0; off >>= 1)
                s += __shfl_xor_sync(0xffffffffu, s, off);
            if (s > e1)       { e2v = e1; j2 = j1; e1 = s; j1 = e; }
            else if (s > e2v) { e2v = s;  j2 = e; }
        }
        if (lane == 0) {
            float ex  = expf(e2v - e1);
            float inv = 1.0f / (1.0f + ex);
            outIdx[tok * 2]     = (float)j1;
            outIdx[tok * 2 + 1] = (float)j2;
            outWgt[tok * 2]     = inv;
            outWgt[tok * 2 + 1] = ex * inv;
        }
    }
}

extern "C" void kernel_launch(void* const* d_in, const int* in_sizes, int n_in,
                              void* d_out, int out_size)
{
    const float* X = (const float*)d_in[0];   // [32768, 2048] fp32
    const float* W = (const float*)d_in[1];   // [64, 2048] fp32
    float* out = (float*)d_out;

    prep_w<<<128, 256>>>(W);

    cudaFuncSetAttribute(router_f16,
                         cudaFuncAttributeMaxDynamicSharedMemorySize, SMEM_BYTES);
    router_f16<<<TOKENS / TILE_M, TPB, SMEM_BYTES>>>(X, out);

    rerank<<<256, 256>>>(X, W, out);
}